// round 7
// baseline (speedup 1.0000x reference)
#include <cuda_runtime.h>
#include <cuda_bf16.h>
#include <cstdint>

// LinearMPC via warp-level mma.sync (bf16 split hi/lo), cluster-of-8 exchange.
// u <- clip(u - s*(uH + f)), 100 iters, B=2048, M=512, H symmetric.

#define MD 512
#define BATCH 2048
#define ITERS 100
#define STEPC 0.01f
#define CLS 8
#define CB 128           // batch rows per cluster
#define NC 64            // H rows (n) per CTA
#define KC 64            // k per u-chunk
#define NCHUNK 8
#define THREADS 256
#define HSTR 1040u       // H smem row stride bytes (1024 + 16 pad)
#define USTR 144u        // u smem row stride bytes (128 + 16 pad)
#define SM_HH 0u
#define SM_HL 66560u     // 64*HSTR
#define SM_U  133120u
#define UPLANE 18432u    // 128*USTR
#define UBUF   36864u    // 2 planes
#define SMEM_TOTAL 206848

__device__ __align__(16) float         g_f [BATCH * MD];
__device__ __align__(16) __nv_bfloat16 g_uh[BATCH * MD];
__device__ __align__(16) __nv_bfloat16 g_ul[BATCH * MD];

__device__ __forceinline__ uint32_t smem_u32_of(const void* p) {
    uint32_t a;
    asm("{ .reg .u64 t; cvta.to.shared.u64 t, %1; cvt.u32.u64 %0, t; }"
        : "=r"(a) : "l"(p));
    return a;
}
__device__ __forceinline__ uint32_t lds32(uint32_t a) {
    uint32_t v;
    asm volatile("ld.shared.b32 %0, [%1];" : "=r"(v) : "r"(a));
    return v;
}
__device__ __forceinline__ void cp16(uint32_t s, const void* g) {
    asm volatile("cp.async.cg.shared.global [%0], [%1], 16;" :: "r"(s), "l"(g));
}
__device__ __forceinline__ void cp_commit() {
    asm volatile("cp.async.commit_group;");
}
template <int N>
__device__ __forceinline__ void cp_wait() {
    asm volatile("cp.async.wait_group %0;" :: "n"(N));
}
__device__ __forceinline__ void cluster_sync() {
    asm volatile("barrier.cluster.arrive.aligned;" ::: "memory");
    asm volatile("barrier.cluster.wait.aligned;" ::: "memory");
}
__device__ __forceinline__ void mma4(float* d, const uint32_t* a,
                                     const uint32_t* b) {
    asm volatile(
        "mma.sync.aligned.m16n8k16.row.col.f32.bf16.bf16.f32 "
        "{%0,%1,%2,%3}, {%4,%5,%6,%7}, {%8,%9}, {%0,%1,%2,%3};"
        : "+f"(d[0]), "+f"(d[1]), "+f"(d[2]), "+f"(d[3])
        : "r"(a[0]), "r"(a[1]), "r"(a[2]), "r"(a[3]), "r"(b[0]), "r"(b[1]));
}
__device__ __forceinline__ uint32_t bfsplit_hi(float x, float& r) {
    __nv_bfloat16 h = __float2bfloat16(x);
    r = x - __bfloat162float(h);
    return (uint32_t)__bfloat16_as_ushort(h);
}

// Prologue: f[b, k*8+i] = -2 * Phi[k] @ Q @ (xref[b,k] - xref[b,0])
__global__ void mpc_f_kernel(const float* __restrict__ xref,
                             const float* __restrict__ Phi,
                             const float* __restrict__ Q) {
    int b = blockIdx.x, k = threadIdx.x;
    const float* xr = xref + (size_t)b * 65 * 8;
    float dx[8], t[8];
#pragma unroll
    for (int l = 0; l < 8; l++) dx[l] = xr[k * 8 + l] - xr[l];
#pragma unroll
    for (int j = 0; j < 8; j++) {
        float s = 0.f;
#pragma unroll
        for (int l = 0; l < 8; l++) s = fmaf(Q[j * 8 + l], dx[l], s);
        t[j] = s;
    }
    const float* Pk = Phi + (size_t)k * 64;
#pragma unroll
    for (int i = 0; i < 8; i++) {
        float s = 0.f;
#pragma unroll
        for (int j = 0; j < 8; j++) s = fmaf(Pk[i * 8 + j], t[j], s);
        g_f[(size_t)b * MD + k * 8 + i] = -2.0f * s;
    }
}

__global__ void __cluster_dims__(CLS, 1, 1) __launch_bounds__(THREADS, 1)
mpc_mma_kernel(const float* __restrict__ Hm, float* __restrict__ out) {
    extern __shared__ char smem[];
    const uint32_t sb = smem_u32_of(smem);
    const int tid = threadIdx.x, lane = tid & 31;
    const int qr = lane >> 2, qc = lane & 3;
    const int wm = (tid >> 5) & 3, wn = tid >> 7;   // 4 m-groups x 2 n-groups
    uint32_t rank;
    asm("mov.u32 %0, %%cluster_ctarank;" : "=r"(rank));
    const int cbase = (int)(blockIdx.x >> 3) * CB;
    const int n0 = (int)rank * NC;

    // ---- Stage H rows [n0, n0+64) as bf16 hi/lo (resident all iterations).
    for (int i = tid * 4; i < NC * MD; i += THREADS * 4) {
        int n = i >> 9, k = i & (MD - 1);
        float4 h = *(const float4*)&Hm[(size_t)(n0 + n) * MD + k];
        float r0, r1, r2, r3;
        uint32_t h0 = bfsplit_hi(h.x, r0), h1 = bfsplit_hi(h.y, r1);
        uint32_t h2 = bfsplit_hi(h.z, r2), h3 = bfsplit_hi(h.w, r3);
        float d0, d1, d2, d3;
        uint32_t l0 = bfsplit_hi(r0, d0), l1 = bfsplit_hi(r1, d1);
        uint32_t l2 = bfsplit_hi(r2, d2), l3 = bfsplit_hi(r3, d3);
        uint32_t off = (uint32_t)n * HSTR + (uint32_t)(k << 1);
        *(uint2*)(smem + SM_HH + off) = make_uint2(h0 | (h1 << 16), h2 | (h3 << 16));
        *(uint2*)(smem + SM_HL + off) = make_uint2(l0 | (l1 << 16), l2 | (l3 << 16));
    }

    // ---- Per-thread fragment coordinates (m16n8k16 C-layout).
    // rows: r = cbase + 32*wm + 16*mf + qr (+8); cols: n0 + 32*wn + 8*nf + 2*qc (+1)
    const int colb = n0 + 32 * wn + 2 * qc;
    float fsv[2][4][4], u_m[2][4][4];
#pragma unroll
    for (int mf = 0; mf < 2; mf++) {
        int r0 = cbase + 32 * wm + 16 * mf + qr;
#pragma unroll
        for (int nf = 0; nf < 4; nf++) {
            float2 a = *(const float2*)&g_f[(size_t)r0 * MD + colb + 8 * nf];
            float2 b = *(const float2*)&g_f[(size_t)(r0 + 8) * MD + colb + 8 * nf];
            fsv[mf][nf][0] = STEPC * a.x;  fsv[mf][nf][1] = STEPC * a.y;
            fsv[mf][nf][2] = STEPC * b.x;  fsv[mf][nf][3] = STEPC * b.y;
#pragma unroll
            for (int c = 0; c < 4; c++)
                u_m[mf][nf][c] = fminf(fmaxf(-fsv[mf][nf][c], -1.f), 1.f);
        }
    }

    // ---- Store u1 (bf16 hi/lo) for the exchange.
#pragma unroll
    for (int mf = 0; mf < 2; mf++) {
        int r0 = cbase + 32 * wm + 16 * mf + qr;
#pragma unroll
        for (int nf = 0; nf < 4; nf++) {
            size_t o0 = (size_t)r0 * MD + colb + 8 * nf;
            size_t o8 = (size_t)(r0 + 8) * MD + colb + 8 * nf;
            float q0, q1, q2, q3;
            uint32_t a0 = bfsplit_hi(u_m[mf][nf][0], q0);
            uint32_t a1 = bfsplit_hi(u_m[mf][nf][1], q1);
            uint32_t a2 = bfsplit_hi(u_m[mf][nf][2], q2);
            uint32_t a3 = bfsplit_hi(u_m[mf][nf][3], q3);
            float z;
            *(uint32_t*)&g_uh[o0] = a0 | (a1 << 16);
            *(uint32_t*)&g_uh[o8] = a2 | (a3 << 16);
            *(uint32_t*)&g_ul[o0] = bfsplit_hi(q0, z) | (bfsplit_hi(q1, z) << 16);
            *(uint32_t*)&g_ul[o8] = bfsplit_hi(q2, z) | (bfsplit_hi(q3, z) << 16);
        }
    }

    // ---- Loader geometry: thread -> (row = tid/2, half = tid&1) of a chunk.
    const int lrow = tid >> 1, lhalf = tid & 1;
    const size_t lsrc = (size_t)(cbase + lrow) * MD + lhalf * 32;
    const uint32_t ldst = sb + SM_U + (uint32_t)lrow * USTR + (uint32_t)lhalf * 64u;

    // fragment LDS base offsets
    const uint32_t aoff = (uint32_t)(32 * wm + qr) * USTR + 4u * qc;
    const uint32_t boff = (uint32_t)(32 * wn + qr) * HSTR + 4u * qc;

    for (int it = 1; it < ITERS; it++) {
        __threadfence();
        cluster_sync();   // all cluster CTAs' u stores visible

        // prefetch chunks 0,1
#pragma unroll
        for (int pc = 0; pc < 2; pc++) {
            const __nv_bfloat16* sh = g_uh + lsrc + pc * KC;
            const __nv_bfloat16* sl = g_ul + lsrc + pc * KC;
            uint32_t d = ldst + (uint32_t)pc * UBUF;
#pragma unroll
            for (int j = 0; j < 4; j++) cp16(d + j * 16, sh + j * 8);
#pragma unroll
            for (int j = 0; j < 4; j++) cp16(d + UPLANE + j * 16, sl + j * 8);
            cp_commit();
        }

        float acc[2][4][4];
#pragma unroll
        for (int mf = 0; mf < 2; mf++)
#pragma unroll
            for (int nf = 0; nf < 4; nf++)
#pragma unroll
                for (int c = 0; c < 4; c++) acc[mf][nf][c] = 0.f;

#pragma unroll 1
        for (int kc = 0; kc < NCHUNK; kc++) {
            if (kc == NCHUNK - 1) cp_wait<0>(); else cp_wait<1>();
            __syncthreads();

            const uint32_t ab = sb + SM_U + (uint32_t)(kc & 1) * UBUF + aoff;
            const uint32_t bb = sb + boff + (uint32_t)kc * 128u;
#pragma unroll
            for (int ks = 0; ks < 4; ks++) {
                uint32_t ah[2][4], al[2][4];
#pragma unroll
                for (int mf = 0; mf < 2; mf++) {
                    uint32_t a0 = ab + mf * (16 * USTR) + 32 * ks;
                    ah[mf][0] = lds32(a0);
                    ah[mf][1] = lds32(a0 + 8 * USTR);
                    ah[mf][2] = lds32(a0 + 16);
                    ah[mf][3] = lds32(a0 + 8 * USTR + 16);
                    uint32_t a1 = a0 + UPLANE;
                    al[mf][0] = lds32(a1);
                    al[mf][1] = lds32(a1 + 8 * USTR);
                    al[mf][2] = lds32(a1 + 16);
                    al[mf][3] = lds32(a1 + 8 * USTR + 16);
                }
#pragma unroll
                for (int nf = 0; nf < 4; nf++) {
                    uint32_t b0 = bb + nf * (8 * HSTR) + 32 * ks;
                    uint32_t bh[2] = { lds32(b0), lds32(b0 + 16) };
                    uint32_t bl[2] = { lds32(b0 + SM_HL), lds32(b0 + SM_HL + 16) };
#pragma unroll
                    for (int mf = 0; mf < 2; mf++) {
                        mma4(acc[mf][nf], ah[mf], bh);
                        mma4(acc[mf][nf], al[mf], bh);
                        mma4(acc[mf][nf], ah[mf], bl);
                    }
                }
            }
            __syncthreads();   // all warps done with buf kc&1
            if (kc + 2 < NCHUNK) {
                const __nv_bfloat16* sh = g_uh + lsrc + (kc + 2) * KC;
                const __nv_bfloat16* sl = g_ul + lsrc + (kc + 2) * KC;
                uint32_t d = ldst + (uint32_t)(kc & 1) * UBUF;
#pragma unroll
                for (int j = 0; j < 4; j++) cp16(d + j * 16, sh + j * 8);
#pragma unroll
                for (int j = 0; j < 4; j++) cp16(d + UPLANE + j * 16, sl + j * 8);
                cp_commit();
            }
        }

        // ---- u <- clip(u - s*acc - fs); store bf16 (or fp32 out on last).
        const bool last = (it == ITERS - 1);
#pragma unroll
        for (int mf = 0; mf < 2; mf++) {
            int r0 = cbase + 32 * wm + 16 * mf + qr;
#pragma unroll
            for (int nf = 0; nf < 4; nf++) {
#pragma unroll
                for (int c = 0; c < 4; c++) {
                    float t = fmaf(-STEPC, acc[mf][nf][c], u_m[mf][nf][c])
                              - fsv[mf][nf][c];
                    u_m[mf][nf][c] = fminf(fmaxf(t, -1.f), 1.f);
                }
                size_t o0 = (size_t)r0 * MD + colb + 8 * nf;
                size_t o8 = (size_t)(r0 + 8) * MD + colb + 8 * nf;
                if (last) {
                    *(float2*)&out[o0] =
                        make_float2(u_m[mf][nf][0], u_m[mf][nf][1]);
                    *(float2*)&out[o8] =
                        make_float2(u_m[mf][nf][2], u_m[mf][nf][3]);
                } else {
                    float q0, q1, q2, q3;
                    uint32_t a0 = bfsplit_hi(u_m[mf][nf][0], q0);
                    uint32_t a1 = bfsplit_hi(u_m[mf][nf][1], q1);
                    uint32_t a2 = bfsplit_hi(u_m[mf][nf][2], q2);
                    uint32_t a3 = bfsplit_hi(u_m[mf][nf][3], q3);
                    float z;
                    *(uint32_t*)&g_uh[o0] = a0 | (a1 << 16);
                    *(uint32_t*)&g_uh[o8] = a2 | (a3 << 16);
                    *(uint32_t*)&g_ul[o0] =
                        bfsplit_hi(q0, z) | (bfsplit_hi(q1, z) << 16);
                    *(uint32_t*)&g_ul[o8] =
                        bfsplit_hi(q2, z) | (bfsplit_hi(q3, z) << 16);
                }
            }
        }
    }
}

extern "C" void kernel_launch(void* const* d_in, const int* in_sizes, int n_in,
                              void* d_out, int out_size) {
    // metadata order: x0, xref, H, Phi, Q
    const float* xref = (const float*)d_in[1];
    const float* H    = (const float*)d_in[2];
    const float* Phi  = (const float*)d_in[3];
    const float* Q    = (const float*)d_in[4];
    float* out        = (float*)d_out;

    cudaFuncSetAttribute(mpc_mma_kernel,
                         cudaFuncAttributeMaxDynamicSharedMemorySize, SMEM_TOTAL);

    mpc_f_kernel<<<BATCH, 64>>>(xref, Phi, Q);
    mpc_mma_kernel<<<(BATCH / CB) * CLS, THREADS, SMEM_TOTAL>>>(H, out);
}